// round 6
// baseline (speedup 1.0000x reference)
#include <cuda_runtime.h>
#include <cuda_fp16.h>
#include <stdint.h>

#define MAXN    1048576        // >= 1,000,000 rows
#define KTAPS   27
#define CIN     32
#define COUT    32
#define MBLOCK  256            // rows per tile (2 m16-tiles x 16 rows per warp)
#define NTHREADS 256
#define NSTRIDE 258            // per-tap stride in nbr_s (even, !=0 mod 32 -> <=2-way STS)

// Scratch (allocation-free): fp16 copy of X with permuted channel pairs, fp16 W.
__device__ __align__(16) __half g_x16[(size_t)MAXN * CIN];            // 64 MiB
__device__ __align__(16) __half g_w16[KTAPS * COUT * CIN];            // [tap][n][k'] 54 KiB
__device__ int g_nbr_is64;                                            // neighbor dtype flag

// Involution on channel-pair index (s in 0..15): sigma(sigma(s)) == s
__device__ __forceinline__ int sigma(int s) { return ((s & 3) << 2) | (s >> 2); }

// ---------------- Neighbor dtype detection (tiny sample) ----------------
__global__ void detect_nbr_kernel(const int* __restrict__ words) {
    int nz = 0;
    #pragma unroll
    for (int j = 0; j < 8; j++)
        nz |= words[2 * (threadIdx.x * 8 + j) + 1];
    int any = __syncthreads_or(nz != 0);
    if (threadIdx.x == 0) g_nbr_is64 = any ? 0 : 1;
}

// ---------------- X conversion: fp32 [N,32] -> fp16 permuted [N,32] ----------------
__global__ void convert_x_kernel(const float* __restrict__ x, int n) {
    long long tid = (long long)blockIdx.x * blockDim.x + threadIdx.x;
    long long total = (long long)n * 16;
    if (tid >= total) return;
    int i = (int)(tid >> 4);
    int s = (int)(tid & 15);
    int p = sigma(s);                          // memory slot s holds original pair sigma(s)
    float2 v = __ldcs((const float2*)(x + (size_t)i * CIN + 2 * p));
    ((__half2*)g_x16)[(size_t)i * 16 + s] = __floats2half2_rn(v.x, v.y);
}

// ---------------- W conversion: fp32 [tap][c][n] -> fp16 [tap][n][k'] ----------------
__global__ void convert_w_kernel(const float* __restrict__ w) {
    int e = blockIdx.x * blockDim.x + threadIdx.x;
    if (e >= KTAPS * COUT * CIN) return;
    int tap = e / (COUT * CIN);
    int rem = e % (COUT * CIN);
    int nn  = rem / CIN;
    int kp  = rem % CIN;                       // permuted k position
    int s   = kp >> 1, bit = kp & 1;
    int c   = 2 * sigma(s) + bit;              // original input channel
    g_w16[e] = __float2half_rn(w[(size_t)tap * CIN * COUT + (size_t)c * COUT + nn]);
}

// ---------------- fp16 MMA m16n8k16, fp32 accumulate ----------------
__device__ __forceinline__ void mma16816(float c[4],
                                         uint32_t a0, uint32_t a1, uint32_t a2, uint32_t a3,
                                         uint32_t b0, uint32_t b1) {
    asm("mma.sync.aligned.m16n8k16.row.col.f32.f16.f16.f32 "
        "{%0,%1,%2,%3}, {%4,%5,%6,%7}, {%8,%9}, {%0,%1,%2,%3};\n"
        : "+f"(c[0]), "+f"(c[1]), "+f"(c[2]), "+f"(c[3])
        : "r"(a0), "r"(a1), "r"(a2), "r"(a3), "r"(b0), "r"(b1));
}

// Map row r (0..255) to its slot in the paired layout:
// slot = warp*32 + mt*16 + j*2 + half, so (r, r+8) land in adjacent ints -> LDS.64
__device__ __forceinline__ int pairpos(int r) {
    return (r & 0xE0) | (r & 16) | ((r & 7) << 1) | ((r >> 3) & 1);
}

// ---------------- Main: persistent blocks, gather + 27-tap MMA, depth-2 pipeline ----
// smem: [0, 55296)          fp16 W (uint4 view, [tap][n-tile-row][16B])
//       [55296, +27864)     int32 neighbor BYTE OFFSETS (idx*64), paired layout
#define W_SMEM     55296
#define SMEM_BYTES (W_SMEM + KTAPS * NSTRIDE * 4)

__global__ __launch_bounds__(NTHREADS, 2)
void conv_main_kernel(const void* __restrict__ nbr_raw,
                      const float* __restrict__ bias,
                      float* __restrict__ out, int n, int ntiles) {
    extern __shared__ uint8_t smem[];
    uint4* w_s4  = (uint4*)smem;
    int*   nbr_s = (int*)(smem + W_SMEM);

    const int tid  = threadIdx.x;
    const int is64 = g_nbr_is64;

    // Stage W once per persistent block (3456 uint4, coalesced)
    const uint4* wg4 = (const uint4*)g_w16;
    #pragma unroll 4
    for (int t = tid; t < 3456; t += NTHREADS) w_s4[t] = wg4[t];

    const int lane = tid & 31;
    const int warp = tid >> 5;
    const int q    = lane & 3;     // quad column (16B chunk within row)
    const int nrow = lane >> 2;    // 0..7
    const int mb   = warp * 32;    // warp's 32 rows within tile
    const int bi   = warp * 32 + nrow * 2;   // pair-slot base (mt adds 16)

    // Staging decomposition: entries t = tid + j*256, j=0..26; 256 = 9*27 + 13
    const int r0 = tid / KTAPS;
    const int k0 = tid - r0 * KTAPS;

    // Bias fragment (kept in regs across tiles)
    float2 bz[4];
    #pragma unroll
    for (int t = 0; t < 4; t++)
        bz[t] = *(const float2*)(bias + t * 8 + 2 * q);

    const char* xb = (const char*)g_x16 + q * 16;   // this thread's chunk base

    #define LOAD_TAP(buf, k) do {                                           \
        _Pragma("unroll")                                                   \
        for (int mt = 0; mt < 2; mt++) {                                    \
            int2 pr = *(const int2*)(nbr_s + (k) * NSTRIDE + bi + mt * 16); \
            (buf)[mt * 2 + 0] = *(const uint4*)(xb + pr.x);                 \
            (buf)[mt * 2 + 1] = *(const uint4*)(xb + pr.y);                 \
        }                                                                   \
    } while (0)

    #define MMA_TAP(buf, k) do {                                            \
        _Pragma("unroll")                                                   \
        for (int t = 0; t < 4; t++) {                                       \
            uint4 bw = w_s4[(k) * 128 + (t * 8 + nrow) * 4 + q];            \
            _Pragma("unroll")                                               \
            for (int mt = 0; mt < 2; mt++) {                                \
                const uint4& lo = (buf)[mt * 2 + 0];                        \
                const uint4& hi = (buf)[mt * 2 + 1];                        \
                mma16816(acc[mt][t], lo.x, hi.x, lo.y, hi.y, bw.x, bw.y);   \
                mma16816(acc[mt][t], lo.z, hi.z, lo.w, hi.w, bw.z, bw.w);   \
            }                                                               \
        }                                                                   \
    } while (0)

    for (int tile = blockIdx.x; tile < ntiles; tile += gridDim.x) {
        const int i0 = tile * MBLOCK;

        __syncthreads();   // previous tile's readers done before nbr_s overwrite
        // Stage neighbor byte-offsets (idx*64) into paired layout; division-free.
        {
            int r = r0, k = k0;
            const size_t gbase = (size_t)i0 * KTAPS + tid;
            if (is64) {
                const long long* nbr = (const long long*)nbr_raw;
                #pragma unroll 1
                for (int j = 0; j < KTAPS; j++) {
                    long long v = (i0 + r < n) ? __ldcs(nbr + gbase + (size_t)j * NTHREADS) : 0;
                    nbr_s[k * NSTRIDE + pairpos(r)] = ((int)v) << 6;
                    r += 9; k += 13; if (k >= KTAPS) { k -= KTAPS; r += 1; }
                }
            } else {
                const int* nbr = (const int*)nbr_raw;
                #pragma unroll 1
                for (int j = 0; j < KTAPS; j++) {
                    int v = (i0 + r < n) ? __ldcs(nbr + gbase + (size_t)j * NTHREADS) : 0;
                    nbr_s[k * NSTRIDE + pairpos(r)] = v << 6;
                    r += 9; k += 13; if (k >= KTAPS) { k -= KTAPS; r += 1; }
                }
            }
        }
        __syncthreads();

        // Acc init = bias
        float acc[2][4][4];
        #pragma unroll
        for (int t = 0; t < 4; t++) {
            #pragma unroll
            for (int mt = 0; mt < 2; mt++) {
                acc[mt][t][0] = bz[t].x; acc[mt][t][1] = bz[t].y;
                acc[mt][t][2] = bz[t].x; acc[mt][t][3] = bz[t].y;
            }
        }

        // Depth-2 software pipeline, 3 rotating register buffers, KTAPS = 9*3.
        uint4 A0[4], A1[4], A2[4];
        LOAD_TAP(A0, 0);
        LOAD_TAP(A1, 1);

        #pragma unroll 1
        for (int kk = 0; kk < KTAPS / 3; kk++) {
            int k = kk * 3;
            if (k + 2 < KTAPS) LOAD_TAP(A2, k + 2);
            MMA_TAP(A0, k);
            if (k + 3 < KTAPS) LOAD_TAP(A0, k + 3);
            MMA_TAP(A1, k + 1);
            if (k + 4 < KTAPS) LOAD_TAP(A1, k + 4);
            MMA_TAP(A2, k + 2);
        }

        // Epilogue: streaming stores (bias already in acc)
        #pragma unroll
        for (int mt = 0; mt < 2; mt++) {
            #pragma unroll
            for (int half = 0; half < 2; half++) {
                int r = i0 + mb + mt * 16 + nrow + half * 8;
                if (r < n) {
                    float* po = out + (size_t)r * COUT + 2 * q;
                    #pragma unroll
                    for (int t = 0; t < 4; t++) {
                        float2 v;
                        v.x = acc[mt][t][half * 2 + 0];
                        v.y = acc[mt][t][half * 2 + 1];
                        __stcs((float2*)(po + t * 8), v);
                    }
                }
            }
        }
    }
}

// ---------------- Launch ----------------
extern "C" void kernel_launch(void* const* d_in, const int* in_sizes, int n_in,
                              void* d_out, int out_size) {
    const float* x    = (const float*)d_in[0];       // [N, 32] f32
    const float* w    = (const float*)d_in[1];       // [27, 32, 32] f32
    const float* bias = (const float*)d_in[2];       // [32] f32
    const void*  nbr  = d_in[3];                     // [N, 27] int32 OR int64 (detected)
    float*       out  = (float*)d_out;               // [N, 32] f32

    const int n = in_sizes[0] / CIN;
    const int ntiles = (n + MBLOCK - 1) / MBLOCK;

    int nsm = 148;
    cudaDeviceGetAttribute(&nsm, cudaDevAttrMultiProcessorCount, 0);
    int grid = 2 * nsm;
    if (grid > ntiles) grid = ntiles;

    cudaFuncSetAttribute(conv_main_kernel,
                         cudaFuncAttributeMaxDynamicSharedMemorySize, SMEM_BYTES);

    detect_nbr_kernel<<<1, 256>>>((const int*)nbr);
    {
        int total = KTAPS * COUT * CIN;
        convert_w_kernel<<<(total + NTHREADS - 1) / NTHREADS, NTHREADS>>>(w);
    }
    {
        long long total = (long long)n * 16;
        int blocks = (int)((total + NTHREADS - 1) / NTHREADS);
        convert_x_kernel<<<blocks, NTHREADS>>>(x, n);
    }
    conv_main_kernel<<<grid, NTHREADS, SMEM_BYTES>>>(nbr, bias, out, n, ntiles);
}

// round 7
// speedup vs baseline: 1.4776x; 1.4776x over previous
#include <cuda_runtime.h>
#include <cuda_fp16.h>
#include <stdint.h>

#define MAXN    1048576        // >= 1,000,000 rows
#define KTAPS   27
#define CIN     32
#define COUT    32
#define MBLOCK  256            // rows per tile (2 m16-tiles x 16 rows per warp)
#define NTHREADS 256
#define NSTRIDE 258            // per-tap stride in nbr_s (even -> LDS.64-aligned)

// Scratch (allocation-free): fp16 copy of X with permuted channel pairs, fp16 W.
__device__ __align__(16) __half g_x16[(size_t)MAXN * CIN];            // 64 MiB
__device__ __align__(16) __half g_w16[KTAPS * COUT * CIN];            // [tap][n][k'] 54 KiB
__device__ int g_nbr_is64;                                            // neighbor dtype flag

// Involution on channel-pair index (s in 0..15): sigma(sigma(s)) == s
__device__ __forceinline__ int sigma(int s) { return ((s & 3) << 2) | (s >> 2); }

// ---------------- Neighbor dtype detection (tiny sample) ----------------
__global__ void detect_nbr_kernel(const int* __restrict__ words) {
    int nz = 0;
    #pragma unroll
    for (int j = 0; j < 8; j++)
        nz |= words[2 * (threadIdx.x * 8 + j) + 1];
    int any = __syncthreads_or(nz != 0);
    if (threadIdx.x == 0) g_nbr_is64 = any ? 0 : 1;
}

// ---------------- X conversion: fp32 [N,32] -> fp16 permuted [N,32] ----------------
__global__ void convert_x_kernel(const float* __restrict__ x, int n) {
    long long tid = (long long)blockIdx.x * blockDim.x + threadIdx.x;
    long long total = (long long)n * 16;
    if (tid >= total) return;
    int i = (int)(tid >> 4);
    int s = (int)(tid & 15);
    int p = sigma(s);                          // memory slot s holds original pair sigma(s)
    float2 v = __ldcs((const float2*)(x + (size_t)i * CIN + 2 * p));
    ((__half2*)g_x16)[(size_t)i * 16 + s] = __floats2half2_rn(v.x, v.y);
}

// ---------------- W conversion: fp32 [tap][c][n] -> fp16 [tap][n][k'] ----------------
__global__ void convert_w_kernel(const float* __restrict__ w) {
    int e = blockIdx.x * blockDim.x + threadIdx.x;
    if (e >= KTAPS * COUT * CIN) return;
    int tap = e / (COUT * CIN);
    int rem = e % (COUT * CIN);
    int nn  = rem / CIN;
    int kp  = rem % CIN;                       // permuted k position
    int s   = kp >> 1, bit = kp & 1;
    int c   = 2 * sigma(s) + bit;              // original input channel
    g_w16[e] = __float2half_rn(w[(size_t)tap * CIN * COUT + (size_t)c * COUT + nn]);
}

// ---------------- fp16 MMA m16n8k16, fp32 accumulate ----------------
__device__ __forceinline__ void mma16816(float c[4],
                                         uint32_t a0, uint32_t a1, uint32_t a2, uint32_t a3,
                                         uint32_t b0, uint32_t b1) {
    asm("mma.sync.aligned.m16n8k16.row.col.f32.f16.f16.f32 "
        "{%0,%1,%2,%3}, {%4,%5,%6,%7}, {%8,%9}, {%0,%1,%2,%3};\n"
        : "+f"(c[0]), "+f"(c[1]), "+f"(c[2]), "+f"(c[3])
        : "r"(a0), "r"(a1), "r"(a2), "r"(a3), "r"(b0), "r"(b1));
}

// Map row r (0..255) to its slot in the paired layout:
// slot = warp*32 + mt*16 + j*2 + half, so (r, r+8) land in adjacent ints -> LDS.64
__device__ __forceinline__ int pairpos(int r) {
    return (r & 0xE0) | (r & 16) | ((r & 7) << 1) | ((r >> 3) & 1);
}

// ---------------- Main: persistent blocks, gather + 27-tap MMA, depth-2 pipeline ----
// smem: [0, 55296)          fp16 W (uint4 view, [tap][n-tile-row][16B])
//       [55296, +27864)     int32 neighbor BYTE OFFSETS (idx*64), paired layout
#define W_SMEM     55296
#define SMEM_BYTES (W_SMEM + KTAPS * NSTRIDE * 4)

__global__ __launch_bounds__(NTHREADS, 2)
void conv_main_kernel(const void* __restrict__ nbr_raw,
                      const float* __restrict__ bias,
                      float* __restrict__ out, int n, int ntiles) {
    extern __shared__ uint8_t smem[];
    uint4* w_s4  = (uint4*)smem;
    int*   nbr_s = (int*)(smem + W_SMEM);

    const int tid  = threadIdx.x;
    const int is64 = g_nbr_is64;

    // Stage W once per persistent block (3456 uint4, coalesced)
    const uint4* wg4 = (const uint4*)g_w16;
    #pragma unroll 4
    for (int t = tid; t < 3456; t += NTHREADS) w_s4[t] = wg4[t];

    const int lane = tid & 31;
    const int warp = tid >> 5;
    const int q    = lane & 3;     // quad column (16B chunk within row)
    const int nrow = lane >> 2;    // 0..7
    const int mb   = warp * 32;    // warp's 32 rows within tile
    const int bi   = warp * 32 + nrow * 2;   // pair-slot base (mt adds 16)

    // Bias fragment (kept in regs across tiles)
    float2 bz[4];
    #pragma unroll
    for (int t = 0; t < 4; t++)
        bz[t] = *(const float2*)(bias + t * 8 + 2 * q);

    const char* xb = (const char*)g_x16 + q * 16;   // this thread's chunk base

    #define LOAD_TAP(buf, k) do {                                           \
        _Pragma("unroll")                                                   \
        for (int mt = 0; mt < 2; mt++) {                                    \
            int2 pr = *(const int2*)(nbr_s + (k) * NSTRIDE + bi + mt * 16); \
            (buf)[mt * 2 + 0] = *(const uint4*)(xb + pr.x);                 \
            (buf)[mt * 2 + 1] = *(const uint4*)(xb + pr.y);                 \
        }                                                                   \
    } while (0)

    #define MMA_TAP(buf, k) do {                                            \
        _Pragma("unroll")                                                   \
        for (int t = 0; t < 4; t++) {                                       \
            uint4 bw = w_s4[(k) * 128 + (t * 8 + nrow) * 4 + q];            \
            _Pragma("unroll")                                               \
            for (int mt = 0; mt < 2; mt++) {                                \
                const uint4& lo = (buf)[mt * 2 + 0];                        \
                const uint4& hi = (buf)[mt * 2 + 1];                        \
                mma16816(acc[mt][t], lo.x, hi.x, lo.y, hi.y, bw.x, bw.y);   \
                mma16816(acc[mt][t], lo.z, hi.z, lo.w, hi.w, bw.z, bw.w);   \
            }                                                               \
        }                                                                   \
    } while (0)

    for (int tile = blockIdx.x; tile < ntiles; tile += gridDim.x) {
        const int i0 = tile * MBLOCK;
        const bool full = (i0 + MBLOCK <= n);

        __syncthreads();   // previous tile's readers done before nbr_s overwrite
        // Stage neighbor byte-offsets (idx*64) into paired layout.
        // Fully unrolled; each j independent (div-by-27 = IMAD.HI) -> LDGs front-batched.
        if (is64) {
            const long long* nbr = (const long long*)nbr_raw;
            const long long* g = nbr + (size_t)i0 * KTAPS + tid;
            if (full) {
                #pragma unroll
                for (int j = 0; j < KTAPS; j++) {
                    int t = tid + j * NTHREADS;
                    int r = t / KTAPS;
                    int k = t - r * KTAPS;
                    nbr_s[k * NSTRIDE + pairpos(r)] = ((int)__ldcs(g + j * NTHREADS)) << 6;
                }
            } else {
                #pragma unroll
                for (int j = 0; j < KTAPS; j++) {
                    int t = tid + j * NTHREADS;
                    int r = t / KTAPS;
                    int k = t - r * KTAPS;
                    long long v = (i0 + r < n) ? __ldcs(g + j * NTHREADS) : 0;
                    nbr_s[k * NSTRIDE + pairpos(r)] = ((int)v) << 6;
                }
            }
        } else {
            const int* nbr = (const int*)nbr_raw;
            const int* g = nbr + (size_t)i0 * KTAPS + tid;
            if (full) {
                #pragma unroll
                for (int j = 0; j < KTAPS; j++) {
                    int t = tid + j * NTHREADS;
                    int r = t / KTAPS;
                    int k = t - r * KTAPS;
                    nbr_s[k * NSTRIDE + pairpos(r)] = __ldcs(g + j * NTHREADS) << 6;
                }
            } else {
                #pragma unroll
                for (int j = 0; j < KTAPS; j++) {
                    int t = tid + j * NTHREADS;
                    int r = t / KTAPS;
                    int k = t - r * KTAPS;
                    int v = (i0 + r < n) ? __ldcs(g + j * NTHREADS) : 0;
                    nbr_s[k * NSTRIDE + pairpos(r)] = v << 6;
                }
            }
        }
        __syncthreads();

        // Acc init = bias
        float acc[2][4][4];
        #pragma unroll
        for (int t = 0; t < 4; t++) {
            #pragma unroll
            for (int mt = 0; mt < 2; mt++) {
                acc[mt][t][0] = bz[t].x; acc[mt][t][1] = bz[t].y;
                acc[mt][t][2] = bz[t].x; acc[mt][t][3] = bz[t].y;
            }
        }

        // Depth-2 software pipeline, 3 rotating register buffers, KTAPS = 9*3.
        uint4 A0[4], A1[4], A2[4];
        LOAD_TAP(A0, 0);
        LOAD_TAP(A1, 1);

        #pragma unroll 1
        for (int kk = 0; kk < KTAPS / 3; kk++) {
            int k = kk * 3;
            if (k + 2 < KTAPS) LOAD_TAP(A2, k + 2);
            MMA_TAP(A0, k);
            if (k + 3 < KTAPS) LOAD_TAP(A0, k + 3);
            MMA_TAP(A1, k + 1);
            if (k + 4 < KTAPS) LOAD_TAP(A1, k + 4);
            MMA_TAP(A2, k + 2);
        }

        // Epilogue: streaming stores (bias already in acc)
        #pragma unroll
        for (int mt = 0; mt < 2; mt++) {
            #pragma unroll
            for (int half = 0; half < 2; half++) {
                int r = i0 + mb + mt * 16 + nrow + half * 8;
                if (full || r < n) {
                    float* po = out + (size_t)r * COUT + 2 * q;
                    #pragma unroll
                    for (int t = 0; t < 4; t++) {
                        float2 v;
                        v.x = acc[mt][t][half * 2 + 0];
                        v.y = acc[mt][t][half * 2 + 1];
                        __stcs((float2*)(po + t * 8), v);
                    }
                }
            }
        }
    }
}

// ---------------- Launch ----------------
extern "C" void kernel_launch(void* const* d_in, const int* in_sizes, int n_in,
                              void* d_out, int out_size) {
    const float* x    = (const float*)d_in[0];       // [N, 32] f32
    const float* w    = (const float*)d_in[1];       // [27, 32, 32] f32
    const float* bias = (const float*)d_in[2];       // [32] f32
    const void*  nbr  = d_in[3];                     // [N, 27] int32 OR int64 (detected)
    float*       out  = (float*)d_out;               // [N, 32] f32

    const int n = in_sizes[0] / CIN;
    const int ntiles = (n + MBLOCK - 1) / MBLOCK;

    int nsm = 148;
    cudaDeviceGetAttribute(&nsm, cudaDevAttrMultiProcessorCount, 0);
    int grid = 2 * nsm;
    if (grid > ntiles) grid = ntiles;

    cudaFuncSetAttribute(conv_main_kernel,
                         cudaFuncAttributeMaxDynamicSharedMemorySize, SMEM_BYTES);

    detect_nbr_kernel<<<1, 256>>>((const int*)nbr);
    {
        int total = KTAPS * COUT * CIN;
        convert_w_kernel<<<(total + NTHREADS - 1) / NTHREADS, NTHREADS>>>(w);
    }
    {
        long long total = (long long)n * 16;
        int blocks = (int)((total + NTHREADS - 1) / NTHREADS);
        convert_x_kernel<<<blocks, NTHREADS>>>(x, n);
    }
    conv_main_kernel<<<grid, NTHREADS, SMEM_BYTES>>>(nbr, bias, out, n, ntiles);
}